// round 16
// baseline (speedup 1.0000x reference)
#include <cuda_runtime.h>

#define D     64
#define CAP   128           // max in-degree bucket (Poisson(16): P(>128) ~ 0)
#define MAX_N 50048
#define LOG2E 1.4426950408889634f
#define AGG_GRID 740        // persistent grid: 148 SMs x 5 CTAs (regs ~52, 256 thr)

// Scratch (allocation-free rule: __device__ globals; zero-initialized at load.
// g_cnt is re-zeroed at the END of each agg iteration, so the zero-invariant
// holds for the correctness call and for every graph replay.)
__device__ float g_pack[MAX_N * 128];   // per node: [ h_src row (64) | feat row (64) ]
__device__ int   g_cnt [MAX_N];         // per-dst degree
__device__ int   g_bkt [MAX_N * CAP];   // src indices bucketed by dst

// ---------------------------------------------------------------------------
// Fused prologue (R13's measured-good version, unchanged): feat GEMM + pack,
// and edge bucketing by dst.
// ---------------------------------------------------------------------------
__global__ void prep_kernel(const float* __restrict__ h,
                            const float* __restrict__ W,
                            const float* __restrict__ b,
                            const int*   __restrict__ src_idx,
                            const int*   __restrict__ dst_idx,
                            int n_src, int E, int feat_blocks) {
    __shared__ float hs[64 * 64];       // 64 rows of h
    __shared__ float Wk[64 * 68];       // W transposed to k-major, padded

    if ((int)blockIdx.x < feat_blocks) {
        const int tid  = threadIdx.x;            // 256 threads
        const int c    = tid & 15;                // col group: cols 4c..4c+3
        const int r0   = tid >> 4;                // row slot 0..15
        const int row0 = blockIdx.x * 64;

        #pragma unroll
        for (int p = 0; p < 4; p++) {
            int idx = tid + p * 256;
            int r   = idx >> 4;
            int k0  = (idx & 15) * 4;
            int row = row0 + r;
            float4 v = (row < n_src)
                     ? *reinterpret_cast<const float4*>(h + (size_t)row * D + k0)
                     : make_float4(0.f, 0.f, 0.f, 0.f);
            *reinterpret_cast<float4*>(&hs[r * 64 + k0]) = v;
        }
        #pragma unroll
        for (int p = 0; p < 4; p++) {
            int idx = tid + p * 256;
            int j   = idx >> 4;
            int k0  = (idx & 15) * 4;
            float4 v = *reinterpret_cast<const float4*>(W + j * 64 + k0);
            Wk[(k0 + 0) * 68 + j] = v.x;
            Wk[(k0 + 1) * 68 + j] = v.y;
            Wk[(k0 + 2) * 68 + j] = v.z;
            Wk[(k0 + 3) * 68 + j] = v.w;
        }
        __syncthreads();

        const float4 bias = reinterpret_cast<const float4*>(b)[c];
        float4 acc[4];
        #pragma unroll
        for (int rr = 0; rr < 4; rr++) acc[rr] = bias;

        #pragma unroll 8
        for (int k = 0; k < 64; k++) {
            const float4 w = *reinterpret_cast<const float4*>(&Wk[k * 68 + c * 4]);
            #pragma unroll
            for (int rr = 0; rr < 4; rr++) {
                const float hk = hs[(r0 + 16 * rr) * 64 + k];
                acc[rr].x = fmaf(hk, w.x, acc[rr].x);
                acc[rr].y = fmaf(hk, w.y, acc[rr].y);
                acc[rr].z = fmaf(hk, w.z, acc[rr].z);
                acc[rr].w = fmaf(hk, w.w, acc[rr].w);
            }
        }

        float4* pack4 = reinterpret_cast<float4*>(g_pack);
        #pragma unroll
        for (int rr = 0; rr < 4; rr++) {
            const int r   = r0 + 16 * rr;
            const int row = row0 + r;
            if (row < n_src) {
                const float4 hv = *reinterpret_cast<const float4*>(&hs[r * 64 + c * 4]);
                pack4[(size_t)row * 32 + c] = hv;
                float4 fv;
                fv.x = fmaxf(acc[rr].x, 0.f);
                fv.y = fmaxf(acc[rr].y, 0.f);
                fv.z = fmaxf(acc[rr].z, 0.f);
                fv.w = fmaxf(acc[rr].w, 0.f);
                pack4[(size_t)row * 32 + 16 + c] = fv;
            }
        }
    } else {
        // scatter: 8 edges/thread
        const int t  = (blockIdx.x - feat_blocks) * blockDim.x + threadIdx.x;
        const int e0 = t * 8;
        if (e0 >= E) return;

        if (e0 + 7 < E) {
            #pragma unroll
            for (int q = 0; q < 2; q++) {
                const int4 d4 = *reinterpret_cast<const int4*>(dst_idx + e0 + q * 4);
                const int4 s4 = *reinterpret_cast<const int4*>(src_idx + e0 + q * 4);
                int p0 = atomicAdd(&g_cnt[d4.x], 1);
                int p1 = atomicAdd(&g_cnt[d4.y], 1);
                int p2 = atomicAdd(&g_cnt[d4.z], 1);
                int p3 = atomicAdd(&g_cnt[d4.w], 1);
                if (p0 < CAP) g_bkt[d4.x * CAP + p0] = s4.x;
                if (p1 < CAP) g_bkt[d4.y * CAP + p1] = s4.y;
                if (p2 < CAP) g_bkt[d4.z * CAP + p2] = s4.z;
                if (p3 < CAP) g_bkt[d4.w * CAP + p3] = s4.w;
            }
        } else {
            for (int e = e0; e < E; e++) {
                int d = dst_idx[e];
                int p = atomicAdd(&g_cnt[d], 1);
                if (p < CAP) g_bkt[d * CAP + p] = src_idx[e];
            }
        }
    }
}

// Per-edge math blocks: ONE base address per edge; feat row at +16 float4s.
#define EDGE0(s)                                                               \
    {                                                                          \
        const float4* p = pack4 + (size_t)(s) * 32 + sub;                      \
        const float4 a = p[0];                                                 \
        const float4 f = p[16];                                                \
        float e;                                                               \
        e = exp2f(a.x * hd0.x); den0.x += e; num0.x = fmaf(f.x, e, num0.x);    \
        e = exp2f(a.y * hd0.y); den0.y += e; num0.y = fmaf(f.y, e, num0.y);    \
        e = exp2f(a.z * hd0.z); den0.z += e; num0.z = fmaf(f.z, e, num0.z);    \
        e = exp2f(a.w * hd0.w); den0.w += e; num0.w = fmaf(f.w, e, num0.w);    \
    }
#define EDGE1(s)                                                               \
    {                                                                          \
        const float4* p = pack4 + (size_t)(s) * 32 + sub;                      \
        const float4 a = p[0];                                                 \
        const float4 f = p[16];                                                \
        float e;                                                               \
        e = exp2f(a.x * hd1.x); den1.x += e; num1.x = fmaf(f.x, e, num1.x);    \
        e = exp2f(a.y * hd1.y); den1.y += e; num1.y = fmaf(f.y, e, num1.y);    \
        e = exp2f(a.z * hd1.z); den1.z += e; num1.z = fmaf(f.z, e, num1.z);    \
        e = exp2f(a.w * hd1.w); den1.w += e; num1.w = fmaf(f.w, e, num1.w);    \
    }

// ---------------------------------------------------------------------------
// Persistent TWO-dst-per-warp segmented reduction: the warp interleaves two
// independent dependency chains (dsts 2p and 2p+1), mutually hiding the
// idx->gather latency that blocked single-dst pipelining across the outer loop.
// Unconditional loop to min(cnt0,cnt1)&~3, predicated remainder to max.
// ---------------------------------------------------------------------------
__global__ void agg_kernel(const float* __restrict__ hdst,
                           float* __restrict__ out, int n_dst) {
    const int lane = threadIdx.x & 31;
    const int sub  = lane & 15;
    const int half = lane >> 4;
    const int warps_total = (gridDim.x * blockDim.x) >> 5;
    const int n_pairs = (n_dst + 1) >> 1;
    const float4* __restrict__ pack4 = reinterpret_cast<const float4*>(g_pack);
    const float4* __restrict__ hdst4 = reinterpret_cast<const float4*>(hdst);
    float4* __restrict__ out4 = reinterpret_cast<float4*>(out);

    for (int pw = (blockIdx.x * blockDim.x + threadIdx.x) >> 5;
         pw < n_pairs; pw += warps_total) {

        const int g0 = pw * 2;
        const int g1 = g0 + 1;
        const bool v1 = g1 < n_dst;
        const int g1r = v1 ? g1 : g0;

        const int cnt0 = min(g_cnt[g0], CAP);
        const int cnt1 = v1 ? min(g_cnt[g1], CAP) : 0;

        float4 hd0 = hdst4[(size_t)g0 * 16 + sub];
        float4 hd1 = hdst4[(size_t)g1r * 16 + sub];
        hd0.x *= LOG2E; hd0.y *= LOG2E; hd0.z *= LOG2E; hd0.w *= LOG2E;
        hd1.x *= LOG2E; hd1.y *= LOG2E; hd1.z *= LOG2E; hd1.w *= LOG2E;

        const int* __restrict__ lst0 = g_bkt + (size_t)g0 * CAP;
        const int* __restrict__ lst1 = lst0 + CAP;

        float4 num0 = make_float4(0.f, 0.f, 0.f, 0.f);
        float4 den0 = make_float4(0.f, 0.f, 0.f, 0.f);
        float4 num1 = make_float4(0.f, 0.f, 0.f, 0.f);
        float4 den1 = make_float4(0.f, 0.f, 0.f, 0.f);

        const int cmin4 = min(cnt0, cnt1) & ~3;
        const int cmax  = max(cnt0, cnt1);
        int j = 0;

        // fast path: both dsts active, all loads unconditional
        for (; j < cmin4; j += 4) {
            const int sA0 = lst0[j + half];
            const int sB0 = lst1[j + half];
            const int sA1 = lst0[j + 2 + half];
            const int sB1 = lst1[j + 2 + half];
            EDGE0(sA0)
            EDGE1(sB0)
            EDGE0(sA1)
            EDGE1(sB1)
        }

        // remainder: predicated per-dst
        for (; j < cmax; j += 4) {
            const int e0 = j + half;
            const int e1 = j + 2 + half;
            const int sA0 = (e0 < cnt0) ? lst0[e0] : -1;
            const int sB0 = (e0 < cnt1) ? lst1[e0] : -1;
            const int sA1 = (e1 < cnt0) ? lst0[e1] : -1;
            const int sB1 = (e1 < cnt1) ? lst1[e1] : -1;
            if (sA0 >= 0) EDGE0(sA0)
            if (sB0 >= 0) EDGE1(sB0)
            if (sA1 >= 0) EDGE0(sA1)
            if (sB1 >= 0) EDGE1(sB1)
        }

        // combine the two halves for both dsts
        const unsigned m = 0xffffffffu;
        num0.x += __shfl_xor_sync(m, num0.x, 16);
        num0.y += __shfl_xor_sync(m, num0.y, 16);
        num0.z += __shfl_xor_sync(m, num0.z, 16);
        num0.w += __shfl_xor_sync(m, num0.w, 16);
        den0.x += __shfl_xor_sync(m, den0.x, 16);
        den0.y += __shfl_xor_sync(m, den0.y, 16);
        den0.z += __shfl_xor_sync(m, den0.z, 16);
        den0.w += __shfl_xor_sync(m, den0.w, 16);
        num1.x += __shfl_xor_sync(m, num1.x, 16);
        num1.y += __shfl_xor_sync(m, num1.y, 16);
        num1.z += __shfl_xor_sync(m, num1.z, 16);
        num1.w += __shfl_xor_sync(m, num1.w, 16);
        den1.x += __shfl_xor_sync(m, den1.x, 16);
        den1.y += __shfl_xor_sync(m, den1.y, 16);
        den1.z += __shfl_xor_sync(m, den1.z, 16);
        den1.w += __shfl_xor_sync(m, den1.w, 16);

        // half 0 writes dst g0; half 1 writes dst g1 (both halves hold full sums)
        const float4 nn = (half == 0) ? num0 : num1;
        const float4 dd = (half == 0) ? den0 : den1;
        const int    go = (half == 0) ? g0 : g1;
        if (half == 0 || v1) {
            float4 r;
            r.x = dd.x > 0.f ? nn.x / dd.x : 0.f;
            r.y = dd.y > 0.f ? nn.y / dd.y : 0.f;
            r.z = dd.z > 0.f ? nn.z / dd.z : 0.f;
            r.w = dd.w > 0.f ? nn.w / dd.w : 0.f;
            out4[(size_t)go * 16 + sub] = r;
        }

        // reset for next graph replay — after all loads for this pair
        if (lane == 0) g_cnt[g0] = 0;
        if (lane == 16 && v1) g_cnt[g1] = 0;
    }
}

// ---------------------------------------------------------------------------
extern "C" void kernel_launch(void* const* d_in, const int* in_sizes, int n_in,
                              void* d_out, int out_size) {
    const float* h_src   = (const float*)d_in[0];
    const float* h_dst   = (const float*)d_in[1];
    const int*   src_idx = (const int*)  d_in[2];
    const int*   dst_idx = (const int*)  d_in[3];
    const float* W_src   = (const float*)d_in[4];
    const float* b_src   = (const float*)d_in[5];
    float*       out     = (float*)d_out;

    const int n_src = in_sizes[0] / D;
    const int E     = in_sizes[2];
    const int n_dst = out_size / D;

    const int feat_blocks    = (n_src + 63) / 64;
    const int scatter_blocks = ((E + 7) / 8 + 255) / 256;

    prep_kernel<<<feat_blocks + scatter_blocks, 256>>>(
        h_src, W_src, b_src, src_idx, dst_idx, n_src, E, feat_blocks);

    agg_kernel<<<AGG_GRID, 256>>>(h_dst, out, n_dst);
}